// round 12
// baseline (speedup 1.0000x reference)
#include <cuda_runtime.h>
#include <cstdint>

#define NN    10000
#define FD    128
#define DEG   32
#define OUTC  128
#define XO    120
#define KK    81
#define KP    88            // padded K: 11 k-steps of 8
#define LDBW  100           // row stride in WORDS; 100 mod 32 == 4 -> conflict-free frags

// ---------------- SMEM layout (bytes) ----------------
#define OFF_BIAS 0                         // 512
#define OFF_NBR  512                       // 32 ints
#define OFF_CNT  640                       // 1 int
#define OFF_A    1024                      // 128*100*4 = 51200
#define OFF_B    (OFF_A + OUTC*LDBW*4)     // 52224
#define BUF_BYTES (XO*LDBW*4)              // 48000
#define SMEM_TOT (OFF_B + 2*BUF_BYTES)     // 148224

__device__ __forceinline__ uint32_t smem_u32(const void* p) {
    uint32_t a;
    asm("{ .reg .u64 t; cvta.to.shared.u64 t, %1; cvt.u32.u64 %0, t; }" : "=r"(a) : "l"(p));
    return a;
}
__device__ __forceinline__ uint32_t lds32(uint32_t addr) {
    uint32_t v; asm volatile("ld.shared.b32 %0, [%1];" : "=r"(v) : "r"(addr)); return v;
}
__device__ __forceinline__ void sts32f(uint32_t addr, float v) {
    asm volatile("st.shared.f32 [%0], %1;" :: "r"(addr), "f"(v) : "memory");
}
__device__ __forceinline__ float to_tf32(float x) {
    float y; asm("cvt.rna.tf32.f32 %0, %1;" : "=f"(y) : "f"(x)); return y;
}
__device__ __forceinline__ void mma_tf32(float* c, const uint32_t* a, uint32_t b0, uint32_t b1) {
    asm volatile("mma.sync.aligned.m16n8k8.row.col.f32.tf32.tf32.f32 "
                 "{%0,%1,%2,%3}, {%4,%5,%6,%7}, {%8,%9}, {%0,%1,%2,%3};"
                 : "+f"(c[0]), "+f"(c[1]), "+f"(c[2]), "+f"(c[3])
                 : "r"(a[0]), "r"(a[1]), "r"(a[2]), "r"(a[3]), "r"(b0), "r"(b1));
}
#define BAR_SYNC(id)  asm volatile("bar.sync %0, %1;" :: "r"(id), "r"(256) : "memory")
#define BAR_PROD()    asm volatile("bar.sync 3, 128;" ::: "memory")

__global__ void __launch_bounds__(256, 1) lgcl_tf32(const float* __restrict__ nf,
                                                    const int*   __restrict__ adj,
                                                    const float* __restrict__ cw,
                                                    const float* __restrict__ cb,
                                                    float* __restrict__ out) {
    extern __shared__ char smc[];
    const uint32_t sa = smem_u32(smc);
    float* bias_s = reinterpret_cast<float*>(smc + OFF_BIAS);
    int*   s_nbr  = reinterpret_cast<int*>(smc + OFF_NBR);
    int*   s_cnt  = reinterpret_cast<int*>(smc + OFF_CNT);

    const int tid  = threadIdx.x;
    const int wid  = tid >> 5;
    const int lane = tid & 31;

    // ---- init: zero A + both B buffers (K-pad cols 81..87 stay zero forever) ----
    for (int i = tid; i < (SMEM_TOT - OFF_A) / 4; i += 256)
        reinterpret_cast<uint32_t*>(smc + OFF_A)[i] = 0;
    if (tid < OUTC) bias_s[tid] = cb[tid];
    __syncthreads();
    // stage weights (tf32-rounded): A[m][k] at OFF_A + (m*LDBW + k)*4
    for (int idx = tid; idx < OUTC * KK; idx += 256) {
        int m = idx / KK, k = idx - m * KK;
        sts32f(sa + OFF_A + (uint32_t)(m * LDBW + k) * 4, to_tf32(cw[idx]));
    }
    __syncthreads();

    int it = 0;

    if (wid >= 4) {
        // ============ PRODUCER (warps 4..7): adj scan + topk + tf32 im2col scatter ======
        const int j = tid - 128;                     // column 0..127
        for (int node = blockIdx.x; node < NN; node += gridDim.x, ++it) {
            const int buf = it & 1;
            const uint32_t bw = sa + OFF_B + (uint32_t)buf * BUF_BYTES;

            // ---- fused adjacency scan into SMEM neighbor list ----
            if (j == 0) *s_cnt = 0;
            BAR_PROD();
            const int4* rp = reinterpret_cast<const int4*>(adj + (size_t)node * NN);
            for (int c = j; c < NN / 4; c += 128) {
                int4 v = rp[c];
                if (v.x | v.y | v.z | v.w) {
                    int base = c * 4;
                    if (v.x) { int s = atomicAdd(s_cnt, 1); if (s < DEG) s_nbr[s] = base + 0; }
                    if (v.y) { int s = atomicAdd(s_cnt, 1); if (s < DEG) s_nbr[s] = base + 1; }
                    if (v.z) { int s = atomicAdd(s_cnt, 1); if (s < DEG) s_nbr[s] = base + 2; }
                    if (v.w) { int s = atomicAdd(s_cnt, 1); if (s < DEG) s_nbr[s] = base + 3; }
                }
            }
            BAR_PROD();
            const int cnt = (*s_cnt < DEG) ? *s_cnt : DEG;

            // ---- per-column top-8 over neighbors (8-deep LDG prefetch) ----
            float tk[8];
#pragma unroll
            for (int k = 0; k < 8; k++) tk[k] = -1e30f;
            int i = 0;
            for (; i + 8 <= cnt; i += 8) {
                float v[8];
#pragma unroll
                for (int q = 0; q < 8; q++)
                    v[q] = __ldg(nf + (size_t)s_nbr[i + q] * FD + j);
#pragma unroll
                for (int q = 0; q < 8; q++) {
                    float x = v[q];
#pragma unroll
                    for (int k = 0; k < 8; k++) { float mx = fmaxf(tk[k], x); x = fminf(tk[k], x); tk[k] = mx; }
                }
            }
            for (; i < cnt; i++) {
                float x = __ldg(nf + (size_t)s_nbr[i] * FD + j);
#pragma unroll
                for (int k = 0; k < 8; k++) { float mx = fmaxf(tk[k], x); x = fminf(tk[k], x); tk[k] = mx; }
            }
            for (i = cnt; i < 8; i++) {              // torch zero-pads rows before topk
                float x = 0.0f;
#pragma unroll
                for (int k = 0; k < 8; k++) { float mx = fmaxf(tk[k], x); x = fminf(tk[k], x); tk[k] = mx; }
            }

            float vals[9];
            vals[0] = nf[(size_t)node * FD + j];     // channel 0: self
#pragma unroll
            for (int k = 0; k < 8; k++) vals[1 + k] = tk[k];

            // column j feeds B[x = j - t][k = c*9 + t]
#pragma unroll
            for (int c = 0; c < 9; c++) {
                float v = to_tf32(vals[c]);
#pragma unroll
                for (int t = 0; t < 9; t++) {
                    int x = j - t;
                    if (x >= 0 && x < XO)
                        sts32f(bw + (uint32_t)(x * LDBW + c * 9 + t) * 4, v);
                }
            }
            BAR_SYNC(1 + buf);                       // publish buffer
        }
    } else {
        // ============ CONSUMER (warps 0..3): 32 M-rows each, single-pass tf32 GEMM ======
        const int l4 = lane >> 2, lc = lane & 3;
        const uint32_t A8  = 8u * LDBW * 4;          // 3200 B
        const uint32_t A16 = 16u * LDBW * 4;         // 6400 B
        const uint32_t aRow = sa + OFF_A + (uint32_t)((wid * 32 + l4) * LDBW + lc) * 4;

        for (int node = blockIdx.x; node < NN; node += gridDim.x, ++it) {
            const int buf = it & 1;
            BAR_SYNC(1 + buf);                       // wait buffer full

            const uint32_t bRow = sa + OFF_B + (uint32_t)buf * BUF_BYTES
                                + (uint32_t)(l4 * LDBW + lc) * 4;

            float C[2][15][4];
#pragma unroll
            for (int mt = 0; mt < 2; mt++)
#pragma unroll
                for (int t = 0; t < 15; t++)
                    C[mt][t][0] = C[mt][t][1] = C[mt][t][2] = C[mt][t][3] = 0.f;

#pragma unroll 1
            for (int ks = 0; ks < KP / 8; ks++) {
                const uint32_t kb = (uint32_t)ks * 32;
                uint32_t a0[4], a1[4];
                a0[0] = lds32(aRow + kb);            a0[1] = lds32(aRow + A8 + kb);
                a0[2] = lds32(aRow + kb + 16);       a0[3] = lds32(aRow + A8 + kb + 16);
                a1[0] = lds32(aRow + A16 + kb);      a1[1] = lds32(aRow + A16 + A8 + kb);
                a1[2] = lds32(aRow + A16 + kb + 16); a1[3] = lds32(aRow + A16 + A8 + kb + 16);
#pragma unroll
                for (int g = 0; g < 15; g++) {
                    uint32_t b0 = lds32(bRow + (uint32_t)g * A8 + kb);
                    uint32_t b1 = lds32(bRow + (uint32_t)g * A8 + kb + 16);
                    mma_tf32(C[0][g], a0, b0, b1);
                    mma_tf32(C[1][g], a1, b0, b1);
                }
            }

            // ---- epilogue: +bias, float2 stores ----
            float* base = out + (size_t)node * (OUTC * XO);
#pragma unroll
            for (int mt = 0; mt < 2; mt++) {
                const int o0 = wid * 32 + mt * 16 + l4;
                const int o1 = o0 + 8;
                const float b0 = bias_s[o0], b1 = bias_s[o1];
                float* p0 = base + o0 * XO + 2 * lc;
                float* p1 = base + o1 * XO + 2 * lc;
#pragma unroll
                for (int t = 0; t < 15; t++) {
                    *reinterpret_cast<float2*>(p0 + t * 8) =
                        make_float2(C[mt][t][0] + b0, C[mt][t][1] + b0);
                    *reinterpret_cast<float2*>(p1 + t * 8) =
                        make_float2(C[mt][t][2] + b1, C[mt][t][3] + b1);
                }
            }
            // buffer reuse safety: producer refills `buf` only after it reaches
            // BAR(1+buf) again, which is strictly after this consumer's arrival there.
        }
    }
}

extern "C" void kernel_launch(void* const* d_in, const int* in_sizes, int n_in,
                              void* d_out, int out_size) {
    const float* nf  = (const float*)d_in[0];
    const int*   adj = (const int*)d_in[1];
    const float* cw  = (const float*)d_in[2];
    const float* cb  = (const float*)d_in[3];
    float* out = (float*)d_out;
    (void)in_sizes; (void)n_in; (void)out_size;

    cudaFuncSetAttribute(lgcl_tf32, cudaFuncAttributeMaxDynamicSharedMemorySize, SMEM_TOT);
    lgcl_tf32<<<152, 256, SMEM_TOT>>>(nf, adj, cw, cb, out);
}

// round 14
// speedup vs baseline: 2.5077x; 2.5077x over previous
#include <cuda_runtime.h>
#include <cstdint>

#define NN    10000
#define FD    128
#define DEG   32
#define OUTC  128
#define XO    120
#define KK    81
#define KP    88            // padded K: 11 k-steps of 8
#define LDBW  100           // row stride in WORDS; 100 mod 32 == 4 -> conflict-free frags

__device__ int g_nbr[NN * DEG];
__device__ int g_cnt[NN];

// ---------------- kernel 1: adjacency row -> neighbor list (full-grid, DRAM-bound) ----
__global__ void __launch_bounds__(256) build_nbr(const int* __restrict__ adj) {
    __shared__ int s_cnt;
    const int row = blockIdx.x;
    if (threadIdx.x == 0) s_cnt = 0;
    __syncthreads();
    const int4* rp = reinterpret_cast<const int4*>(adj + (size_t)row * NN);
    for (int c = threadIdx.x; c < NN / 4; c += 256) {
        int4 v = rp[c];
        int base = c * 4;
        if (v.x) { int s = atomicAdd(&s_cnt, 1); if (s < DEG) g_nbr[row * DEG + s] = base + 0; }
        if (v.y) { int s = atomicAdd(&s_cnt, 1); if (s < DEG) g_nbr[row * DEG + s] = base + 1; }
        if (v.z) { int s = atomicAdd(&s_cnt, 1); if (s < DEG) g_nbr[row * DEG + s] = base + 2; }
        if (v.w) { int s = atomicAdd(&s_cnt, 1); if (s < DEG) g_nbr[row * DEG + s] = base + 3; }
    }
    __syncthreads();
    if (threadIdx.x == 0) g_cnt[row] = (s_cnt < DEG) ? s_cnt : DEG;
}

// ---------------- SMEM layout (bytes) ----------------
#define OFF_BIAS 0                         // 512
#define OFF_A    1024                      // 128*100*4 = 51200
#define OFF_B    (OFF_A + OUTC*LDBW*4)     // 52224
#define BUF_BYTES (XO*LDBW*4)              // 48000
#define SMEM_TOT (OFF_B + 2*BUF_BYTES)     // 148224

__device__ __forceinline__ uint32_t smem_u32(const void* p) {
    uint32_t a;
    asm("{ .reg .u64 t; cvta.to.shared.u64 t, %1; cvt.u32.u64 %0, t; }" : "=r"(a) : "l"(p));
    return a;
}
__device__ __forceinline__ uint32_t lds32(uint32_t addr) {
    uint32_t v; asm volatile("ld.shared.b32 %0, [%1];" : "=r"(v) : "r"(addr)); return v;
}
__device__ __forceinline__ void sts32f(uint32_t addr, float v) {
    asm volatile("st.shared.f32 [%0], %1;" :: "r"(addr), "f"(v) : "memory");
}
__device__ __forceinline__ float to_tf32(float x) {
    float y; asm("cvt.rna.tf32.f32 %0, %1;" : "=f"(y) : "f"(x)); return y;
}
__device__ __forceinline__ void mma_tf32(float* c, const uint32_t* a, uint32_t b0, uint32_t b1) {
    asm volatile("mma.sync.aligned.m16n8k8.row.col.f32.tf32.tf32.f32 "
                 "{%0,%1,%2,%3}, {%4,%5,%6,%7}, {%8,%9}, {%0,%1,%2,%3};"
                 : "+f"(c[0]), "+f"(c[1]), "+f"(c[2]), "+f"(c[3])
                 : "r"(a[0]), "r"(a[1]), "r"(a[2]), "r"(a[3]), "r"(b0), "r"(b1));
}
#define BAR_SYNC(id)  asm volatile("bar.sync %0, %1;" :: "r"(id), "r"(256) : "memory")

__global__ void __launch_bounds__(256, 1) lgcl_tf32(const float* __restrict__ nf,
                                                    const float* __restrict__ cw,
                                                    const float* __restrict__ cb,
                                                    float* __restrict__ out) {
    extern __shared__ char smc[];
    const uint32_t sa = smem_u32(smc);
    float* bias_s = reinterpret_cast<float*>(smc + OFF_BIAS);

    const int tid  = threadIdx.x;
    const int wid  = tid >> 5;
    const int lane = tid & 31;

    // ---- init: zero A + both B buffers (K-pad cols 81..87 stay zero forever) ----
    for (int i = tid; i < (SMEM_TOT - OFF_A) / 4; i += 256)
        reinterpret_cast<uint32_t*>(smc + OFF_A)[i] = 0;
    if (tid < OUTC) bias_s[tid] = cb[tid];
    __syncthreads();
    // stage weights (tf32-rounded): A[m][k] at OFF_A + (m*LDBW + k)*4
    for (int idx = tid; idx < OUTC * KK; idx += 256) {
        int m = idx / KK, k = idx - m * KK;
        sts32f(sa + OFF_A + (uint32_t)(m * LDBW + k) * 4, to_tf32(cw[idx]));
    }
    __syncthreads();

    int it = 0;

    if (wid >= 4) {
        // ============ PRODUCER (warps 4..7): topk + tf32 im2col scatter ============
        const int j = tid - 128;                     // column 0..127
        for (int node = blockIdx.x; node < NN; node += gridDim.x, ++it) {
            const int buf = it & 1;
            const uint32_t bw = sa + OFF_B + (uint32_t)buf * BUF_BYTES;

            const int cnt = g_cnt[node];
            float tk[8];
#pragma unroll
            for (int k = 0; k < 8; k++) tk[k] = -1e30f;
            int i = 0;
            for (; i + 8 <= cnt; i += 8) {
                int nb8[8];
#pragma unroll
                for (int q = 0; q < 8; q++) nb8[q] = g_nbr[node * DEG + i + q];
                float v[8];
#pragma unroll
                for (int q = 0; q < 8; q++) v[q] = __ldg(nf + (size_t)nb8[q] * FD + j);
#pragma unroll
                for (int q = 0; q < 8; q++) {
                    float x = v[q];
#pragma unroll
                    for (int k = 0; k < 8; k++) { float mx = fmaxf(tk[k], x); x = fminf(tk[k], x); tk[k] = mx; }
                }
            }
            for (; i < cnt; i++) {
                float x = __ldg(nf + (size_t)g_nbr[node * DEG + i] * FD + j);
#pragma unroll
                for (int k = 0; k < 8; k++) { float mx = fmaxf(tk[k], x); x = fminf(tk[k], x); tk[k] = mx; }
            }
            for (i = cnt; i < 8; i++) {              // torch zero-pads rows before topk
                float x = 0.0f;
#pragma unroll
                for (int k = 0; k < 8; k++) { float mx = fmaxf(tk[k], x); x = fminf(tk[k], x); tk[k] = mx; }
            }

            float vals[9];
            vals[0] = nf[(size_t)node * FD + j];     // channel 0: self
#pragma unroll
            for (int k = 0; k < 8; k++) vals[1 + k] = tk[k];

            // column j feeds B[x = j - t][k = c*9 + t]
#pragma unroll
            for (int c = 0; c < 9; c++) {
                float v = to_tf32(vals[c]);
#pragma unroll
                for (int t = 0; t < 9; t++) {
                    int x = j - t;
                    if (x >= 0 && x < XO)
                        sts32f(bw + (uint32_t)(x * LDBW + c * 9 + t) * 4, v);
                }
            }
            BAR_SYNC(1 + buf);                       // publish buffer
        }
    } else {
        // ============ CONSUMER (warps 0..3): 32 M-rows each, single-pass tf32 GEMM =====
        const int l4 = lane >> 2, lc = lane & 3;
        const uint32_t A8  = 8u * LDBW * 4;          // 3200 B
        const uint32_t A16 = 16u * LDBW * 4;         // 6400 B
        const uint32_t aRow = sa + OFF_A + (uint32_t)((wid * 32 + l4) * LDBW + lc) * 4;

        for (int node = blockIdx.x; node < NN; node += gridDim.x, ++it) {
            const int buf = it & 1;
            BAR_SYNC(1 + buf);                       // wait buffer full

            const uint32_t bRow = sa + OFF_B + (uint32_t)buf * BUF_BYTES
                                + (uint32_t)(l4 * LDBW + lc) * 4;

            float C[2][15][4];
#pragma unroll
            for (int mt = 0; mt < 2; mt++)
#pragma unroll
                for (int t = 0; t < 15; t++)
                    C[mt][t][0] = C[mt][t][1] = C[mt][t][2] = C[mt][t][3] = 0.f;

            // fully unrolled k-loop: lets ptxas batch LDS ahead of MMAs (ILP is the
            // only latency hiding available -- one consumer warp per SMSP)
#pragma unroll
            for (int ks = 0; ks < KP / 8; ks++) {
                const uint32_t kb = (uint32_t)ks * 32;
                uint32_t a0[4], a1[4];
                a0[0] = lds32(aRow + kb);            a0[1] = lds32(aRow + A8 + kb);
                a0[2] = lds32(aRow + kb + 16);       a0[3] = lds32(aRow + A8 + kb + 16);
                a1[0] = lds32(aRow + A16 + kb);      a1[1] = lds32(aRow + A16 + A8 + kb);
                a1[2] = lds32(aRow + A16 + kb + 16); a1[3] = lds32(aRow + A16 + A8 + kb + 16);
                uint32_t bf[15][2];
#pragma unroll
                for (int g = 0; g < 15; g++) {
                    bf[g][0] = lds32(bRow + (uint32_t)g * A8 + kb);
                    bf[g][1] = lds32(bRow + (uint32_t)g * A8 + kb + 16);
                }
#pragma unroll
                for (int g = 0; g < 15; g++) {
                    mma_tf32(C[0][g], a0, bf[g][0], bf[g][1]);
                    mma_tf32(C[1][g], a1, bf[g][0], bf[g][1]);
                }
            }

            // ---- epilogue: +bias, float2 stores ----
            float* base = out + (size_t)node * (OUTC * XO);
#pragma unroll
            for (int mt = 0; mt < 2; mt++) {
                const int o0 = wid * 32 + mt * 16 + l4;
                const int o1 = o0 + 8;
                const float b0 = bias_s[o0], b1 = bias_s[o1];
                float* p0 = base + o0 * XO + 2 * lc;
                float* p1 = base + o1 * XO + 2 * lc;
#pragma unroll
                for (int t = 0; t < 15; t++) {
                    *reinterpret_cast<float2*>(p0 + t * 8) =
                        make_float2(C[mt][t][0] + b0, C[mt][t][1] + b0);
                    *reinterpret_cast<float2*>(p1 + t * 8) =
                        make_float2(C[mt][t][2] + b1, C[mt][t][3] + b1);
                }
            }
            // buffer reuse safety: producer refills `buf` only after it reaches
            // BAR(1+buf) again, strictly after this consumer's arrival there.
        }
    }
}

extern "C" void kernel_launch(void* const* d_in, const int* in_sizes, int n_in,
                              void* d_out, int out_size) {
    const float* nf  = (const float*)d_in[0];
    const int*   adj = (const int*)d_in[1];
    const float* cw  = (const float*)d_in[2];
    const float* cb  = (const float*)d_in[3];
    float* out = (float*)d_out;
    (void)in_sizes; (void)n_in; (void)out_size;

    cudaFuncSetAttribute(lgcl_tf32, cudaFuncAttributeMaxDynamicSharedMemorySize, SMEM_TOT);

    build_nbr<<<NN, 256>>>(adj);
    lgcl_tf32<<<152, 256, SMEM_TOT>>>(nf, cw, cb, out);
}

// round 15
// speedup vs baseline: 2.9671x; 1.1832x over previous
#include <cuda_runtime.h>
#include <cstdint>

#define NN    10000
#define FD    128
#define DEG   32
#define OUTC  128
#define XO    120
#define KK    81
#define KP    88            // padded K: 11 k-steps of 8
#define LDBW  100           // row stride in WORDS; 100 mod 32 == 4 -> conflict-free frags
#define NTH   384           // 8 consumer warps + 4 producer warps

__device__ int g_nbr[NN * DEG];
__device__ int g_cnt[NN];

// ---------------- kernel 1: adjacency row -> neighbor list (full-grid, DRAM-bound) ----
__global__ void __launch_bounds__(256) build_nbr(const int* __restrict__ adj) {
    __shared__ int s_cnt;
    const int row = blockIdx.x;
    if (threadIdx.x == 0) s_cnt = 0;
    __syncthreads();
    const int4* rp = reinterpret_cast<const int4*>(adj + (size_t)row * NN);
    for (int c = threadIdx.x; c < NN / 4; c += 256) {
        int4 v = rp[c];
        int base = c * 4;
        if (v.x) { int s = atomicAdd(&s_cnt, 1); if (s < DEG) g_nbr[row * DEG + s] = base + 0; }
        if (v.y) { int s = atomicAdd(&s_cnt, 1); if (s < DEG) g_nbr[row * DEG + s] = base + 1; }
        if (v.z) { int s = atomicAdd(&s_cnt, 1); if (s < DEG) g_nbr[row * DEG + s] = base + 2; }
        if (v.w) { int s = atomicAdd(&s_cnt, 1); if (s < DEG) g_nbr[row * DEG + s] = base + 3; }
    }
    __syncthreads();
    if (threadIdx.x == 0) g_cnt[row] = (s_cnt < DEG) ? s_cnt : DEG;
}

// ---------------- SMEM layout (bytes) ----------------
#define OFF_BIAS 0                         // 512
#define OFF_A    1024                      // 128*100*4 = 51200
#define OFF_B    (OFF_A + OUTC*LDBW*4)     // 52224
#define BUF_BYTES (XO*LDBW*4)              // 48000
#define SMEM_TOT (OFF_B + 2*BUF_BYTES)     // 148224

__device__ __forceinline__ uint32_t smem_u32(const void* p) {
    uint32_t a;
    asm("{ .reg .u64 t; cvta.to.shared.u64 t, %1; cvt.u32.u64 %0, t; }" : "=r"(a) : "l"(p));
    return a;
}
__device__ __forceinline__ uint32_t lds32(uint32_t addr) {
    uint32_t v; asm volatile("ld.shared.b32 %0, [%1];" : "=r"(v) : "r"(addr)); return v;
}
__device__ __forceinline__ void sts32f(uint32_t addr, float v) {
    asm volatile("st.shared.f32 [%0], %1;" :: "r"(addr), "f"(v) : "memory");
}
__device__ __forceinline__ float to_tf32(float x) {
    float y; asm("cvt.rna.tf32.f32 %0, %1;" : "=f"(y) : "f"(x)); return y;
}
__device__ __forceinline__ void mma_tf32(float* c, const uint32_t* a, uint32_t b0, uint32_t b1) {
    asm volatile("mma.sync.aligned.m16n8k8.row.col.f32.tf32.tf32.f32 "
                 "{%0,%1,%2,%3}, {%4,%5,%6,%7}, {%8,%9}, {%0,%1,%2,%3};"
                 : "+f"(c[0]), "+f"(c[1]), "+f"(c[2]), "+f"(c[3])
                 : "r"(a[0]), "r"(a[1]), "r"(a[2]), "r"(a[3]), "r"(b0), "r"(b1));
}
#define BAR_SYNC(id)  asm volatile("bar.sync %0, %1;" :: "r"(id), "r"(NTH) : "memory")

__global__ void __launch_bounds__(NTH, 1) lgcl_tf32(const float* __restrict__ nf,
                                                    const float* __restrict__ cw,
                                                    const float* __restrict__ cb,
                                                    float* __restrict__ out) {
    extern __shared__ char smc[];
    const uint32_t sa = smem_u32(smc);
    float* bias_s = reinterpret_cast<float*>(smc + OFF_BIAS);

    const int tid  = threadIdx.x;
    const int wid  = tid >> 5;
    const int lane = tid & 31;

    // ---- init: zero A + both B buffers (K-pad cols 81..87 stay zero forever) ----
    for (int i = tid; i < (SMEM_TOT - OFF_A) / 4; i += NTH)
        reinterpret_cast<uint32_t*>(smc + OFF_A)[i] = 0;
    if (tid < OUTC) bias_s[tid] = cb[tid];
    __syncthreads();
    // stage weights (tf32-rounded): A[m][k] at OFF_A + (m*LDBW + k)*4
    for (int idx = tid; idx < OUTC * KK; idx += NTH) {
        int m = idx / KK, k = idx - m * KK;
        sts32f(sa + OFF_A + (uint32_t)(m * LDBW + k) * 4, to_tf32(cw[idx]));
    }
    __syncthreads();

    int it = 0;

    if (wid >= 8) {
        // ======== PRODUCER (warps 8..11): topk (16-deep MLP) + tf32 im2col scatter =====
        const int j = tid - 256;                     // column 0..127
        for (int node = blockIdx.x; node < NN; node += gridDim.x, ++it) {
            const int buf = it & 1;
            const uint32_t bw = sa + OFF_B + (uint32_t)buf * BUF_BYTES;

            const int cnt = g_cnt[node];
            float tk[8];
#pragma unroll
            for (int k = 0; k < 8; k++) tk[k] = -1e30f;
            int i = 0;
            for (; i + 16 <= cnt; i += 16) {          // 16-deep prefetch batches
                int nb[16];
#pragma unroll
                for (int q = 0; q < 16; q++) nb[q] = g_nbr[node * DEG + i + q];
                float v[16];
#pragma unroll
                for (int q = 0; q < 16; q++) v[q] = __ldg(nf + (size_t)nb[q] * FD + j);
#pragma unroll
                for (int q = 0; q < 16; q++) {
                    float x = v[q];
#pragma unroll
                    for (int k = 0; k < 8; k++) { float mx = fmaxf(tk[k], x); x = fminf(tk[k], x); tk[k] = mx; }
                }
            }
            for (; i + 8 <= cnt; i += 8) {
                int nb[8];
#pragma unroll
                for (int q = 0; q < 8; q++) nb[q] = g_nbr[node * DEG + i + q];
                float v[8];
#pragma unroll
                for (int q = 0; q < 8; q++) v[q] = __ldg(nf + (size_t)nb[q] * FD + j);
#pragma unroll
                for (int q = 0; q < 8; q++) {
                    float x = v[q];
#pragma unroll
                    for (int k = 0; k < 8; k++) { float mx = fmaxf(tk[k], x); x = fminf(tk[k], x); tk[k] = mx; }
                }
            }
            for (; i < cnt; i++) {
                float x = __ldg(nf + (size_t)g_nbr[node * DEG + i] * FD + j);
#pragma unroll
                for (int k = 0; k < 8; k++) { float mx = fmaxf(tk[k], x); x = fminf(tk[k], x); tk[k] = mx; }
            }
            for (i = cnt; i < 8; i++) {               // torch zero-pads rows before topk
                float x = 0.0f;
#pragma unroll
                for (int k = 0; k < 8; k++) { float mx = fmaxf(tk[k], x); x = fminf(tk[k], x); tk[k] = mx; }
            }

            float vals[9];
            vals[0] = nf[(size_t)node * FD + j];      // channel 0: self
#pragma unroll
            for (int k = 0; k < 8; k++) vals[1 + k] = tk[k];

            // column j feeds B[x = j - t][k = c*9 + t]
#pragma unroll
            for (int c = 0; c < 9; c++) {
                float v = to_tf32(vals[c]);
#pragma unroll
                for (int t = 0; t < 9; t++) {
                    int x = j - t;
                    if (x >= 0 && x < XO)
                        sts32f(bw + (uint32_t)(x * LDBW + c * 9 + t) * 4, v);
                }
            }
            BAR_SYNC(1 + buf);                        // publish buffer
        }
    } else {
        // ======== CONSUMER (warps 0..7): 16 M-rows each, single-pass tf32 GEMM =========
        const int l4 = lane >> 2, lc = lane & 3;
        const uint32_t A8  = 8u * LDBW * 4;           // 3200 B
        const uint32_t aRow = sa + OFF_A + (uint32_t)((wid * 16 + l4) * LDBW + lc) * 4;

        for (int node = blockIdx.x; node < NN; node += gridDim.x, ++it) {
            const int buf = it & 1;
            BAR_SYNC(1 + buf);                        // wait buffer full

            const uint32_t bRow = sa + OFF_B + (uint32_t)buf * BUF_BYTES
                                + (uint32_t)(l4 * LDBW + lc) * 4;

            float C[15][4];
#pragma unroll
            for (int t = 0; t < 15; t++)
                C[t][0] = C[t][1] = C[t][2] = C[t][3] = 0.f;

#pragma unroll
            for (int ks = 0; ks < KP / 8; ks++) {
                const uint32_t kb = (uint32_t)ks * 32;
                uint32_t a[4];
                a[0] = lds32(aRow + kb);        a[1] = lds32(aRow + A8 + kb);
                a[2] = lds32(aRow + kb + 16);   a[3] = lds32(aRow + A8 + kb + 16);
                uint32_t bf[15][2];
#pragma unroll
                for (int g = 0; g < 15; g++) {
                    bf[g][0] = lds32(bRow + (uint32_t)g * A8 + kb);
                    bf[g][1] = lds32(bRow + (uint32_t)g * A8 + kb + 16);
                }
#pragma unroll
                for (int g = 0; g < 15; g++)
                    mma_tf32(C[g], a, bf[g][0], bf[g][1]);
            }

            // ---- epilogue: +bias, float2 stores ----
            float* base = out + (size_t)node * (OUTC * XO);
            const int o0 = wid * 16 + l4;
            const int o1 = o0 + 8;
            const float b0 = bias_s[o0], b1 = bias_s[o1];
            float* p0 = base + o0 * XO + 2 * lc;
            float* p1 = base + o1 * XO + 2 * lc;
#pragma unroll
            for (int t = 0; t < 15; t++) {
                *reinterpret_cast<float2*>(p0 + t * 8) = make_float2(C[t][0] + b0, C[t][1] + b0);
                *reinterpret_cast<float2*>(p1 + t * 8) = make_float2(C[t][2] + b1, C[t][3] + b1);
            }
            // buffer reuse safety: producer refills `buf` only after it reaches
            // BAR(1+buf) again, strictly after this consumer's arrival there.
        }
    }
}

extern "C" void kernel_launch(void* const* d_in, const int* in_sizes, int n_in,
                              void* d_out, int out_size) {
    const float* nf  = (const float*)d_in[0];
    const int*   adj = (const int*)d_in[1];
    const float* cw  = (const float*)d_in[2];
    const float* cb  = (const float*)d_in[3];
    float* out = (float*)d_out;
    (void)in_sizes; (void)n_in; (void)out_size;

    cudaFuncSetAttribute(lgcl_tf32, cudaFuncAttributeMaxDynamicSharedMemorySize, SMEM_TOT);

    build_nbr<<<NN, 256>>>(adj);
    lgcl_tf32<<<152, NTH, SMEM_TOT>>>(nf, cw, cb, out);
}

// round 16
// speedup vs baseline: 3.1822x; 1.0725x over previous
#include <cuda_runtime.h>
#include <cstdint>

#define NN    10000
#define FD    128
#define DEG   32
#define OUTC  128
#define XO    120
#define KK    81
#define KP    88            // padded K: 11 k-steps of 8
#define LDBW  100           // A row stride (words); 100 mod 32 == 4 -> conflict-free frags
#define LDX   132           // B row stride (words); 132 mod 32 == 4 -> conflict-free frags
#define NTH   384           // 8 consumer warps + 4 producer warps

__device__ int g_nbr[NN * DEG];
__device__ int g_cnt[NN];

// ---------------- kernel 1: adjacency row -> neighbor list (full-grid, DRAM-bound) ----
__global__ void __launch_bounds__(256) build_nbr(const int* __restrict__ adj) {
    __shared__ int s_cnt;
    const int row = blockIdx.x;
    if (threadIdx.x == 0) s_cnt = 0;
    __syncthreads();
    const int4* rp = reinterpret_cast<const int4*>(adj + (size_t)row * NN);
    for (int c = threadIdx.x; c < NN / 4; c += 256) {
        int4 v = rp[c];
        int base = c * 4;
        if (v.x) { int s = atomicAdd(&s_cnt, 1); if (s < DEG) g_nbr[row * DEG + s] = base + 0; }
        if (v.y) { int s = atomicAdd(&s_cnt, 1); if (s < DEG) g_nbr[row * DEG + s] = base + 1; }
        if (v.z) { int s = atomicAdd(&s_cnt, 1); if (s < DEG) g_nbr[row * DEG + s] = base + 2; }
        if (v.w) { int s = atomicAdd(&s_cnt, 1); if (s < DEG) g_nbr[row * DEG + s] = base + 3; }
    }
    __syncthreads();
    if (threadIdx.x == 0) g_cnt[row] = (s_cnt < DEG) ? s_cnt : DEG;
}

// ---------------- SMEM layout (bytes) ----------------
#define OFF_BIAS 0                          // 512
#define OFF_A    1024                       // 128*100*4 = 51200
#define OFF_B    (OFF_A + OUTC*LDBW*4)      // 52224
#define BUF_BYTES (KP*LDX*4)                // 46464 (B stored [k][x], transposed)
#define SMEM_TOT (OFF_B + 2*BUF_BYTES)      // 145152

__device__ __forceinline__ uint32_t smem_u32(const void* p) {
    uint32_t a;
    asm("{ .reg .u64 t; cvta.to.shared.u64 t, %1; cvt.u32.u64 %0, t; }" : "=r"(a) : "l"(p));
    return a;
}
__device__ __forceinline__ uint32_t lds32(uint32_t addr) {
    uint32_t v; asm volatile("ld.shared.b32 %0, [%1];" : "=r"(v) : "r"(addr)); return v;
}
__device__ __forceinline__ void sts32f(uint32_t addr, float v) {
    asm volatile("st.shared.f32 [%0], %1;" :: "r"(addr), "f"(v) : "memory");
}
__device__ __forceinline__ float to_tf32(float x) {
    float y; asm("cvt.rna.tf32.f32 %0, %1;" : "=f"(y) : "f"(x)); return y;
}
__device__ __forceinline__ void mma_tf32(float* c, const uint32_t* a, uint32_t b0, uint32_t b1) {
    asm volatile("mma.sync.aligned.m16n8k8.row.col.f32.tf32.tf32.f32 "
                 "{%0,%1,%2,%3}, {%4,%5,%6,%7}, {%8,%9}, {%0,%1,%2,%3};"
                 : "+f"(c[0]), "+f"(c[1]), "+f"(c[2]), "+f"(c[3])
                 : "r"(a[0]), "r"(a[1]), "r"(a[2]), "r"(a[3]), "r"(b0), "r"(b1));
}
#define BAR_SYNC(id)  asm volatile("bar.sync %0, %1;" :: "r"(id), "r"(NTH) : "memory")

__global__ void __launch_bounds__(NTH, 1) lgcl_tf32(const float* __restrict__ nf,
                                                    const float* __restrict__ cw,
                                                    const float* __restrict__ cb,
                                                    float* __restrict__ out) {
    extern __shared__ char smc[];
    const uint32_t sa = smem_u32(smc);
    float* bias_s = reinterpret_cast<float*>(smc + OFF_BIAS);

    const int tid  = threadIdx.x;
    const int wid  = tid >> 5;
    const int lane = tid & 31;

    // ---- init: zero A + both B buffers once.
    // A pad cols 81..87 and B pad k-rows 81..87 (+ never-written x tails) stay zero:
    // producers only ever write k<=80, and k-row (c,t) only gets x in [0, 127-t].
    for (int i = tid; i < (SMEM_TOT - OFF_A) / 4; i += NTH)
        reinterpret_cast<uint32_t*>(smc + OFF_A)[i] = 0;
    if (tid < OUTC) bias_s[tid] = cb[tid];
    __syncthreads();
    // stage weights (tf32-rounded): A[m][k] at OFF_A + (m*LDBW + k)*4
    for (int idx = tid; idx < OUTC * KK; idx += NTH) {
        int m = idx / KK, k = idx - m * KK;
        sts32f(sa + OFF_A + (uint32_t)(m * LDBW + k) * 4, to_tf32(cw[idx]));
    }
    __syncthreads();

    int it = 0;

    if (wid >= 8) {
        // ======== PRODUCER (warps 8..11): topk (16-deep MLP) + transposed im2col =======
        const int j = tid - 256;                     // column 0..127
        for (int node = blockIdx.x; node < NN; node += gridDim.x, ++it) {
            const int buf = it & 1;
            const uint32_t bw = sa + OFF_B + (uint32_t)buf * BUF_BYTES;

            const int cnt = g_cnt[node];
            float tk[8];
#pragma unroll
            for (int k = 0; k < 8; k++) tk[k] = -1e30f;
            int i = 0;
            for (; i + 16 <= cnt; i += 16) {          // 16-deep prefetch batches
                int nb[16];
#pragma unroll
                for (int q = 0; q < 16; q++) nb[q] = g_nbr[node * DEG + i + q];
                float v[16];
#pragma unroll
                for (int q = 0; q < 16; q++) v[q] = __ldg(nf + (size_t)nb[q] * FD + j);
#pragma unroll
                for (int q = 0; q < 16; q++) {
                    float x = v[q];
#pragma unroll
                    for (int k = 0; k < 8; k++) { float mx = fmaxf(tk[k], x); x = fminf(tk[k], x); tk[k] = mx; }
                }
            }
            for (; i + 8 <= cnt; i += 8) {
                int nb[8];
#pragma unroll
                for (int q = 0; q < 8; q++) nb[q] = g_nbr[node * DEG + i + q];
                float v[8];
#pragma unroll
                for (int q = 0; q < 8; q++) v[q] = __ldg(nf + (size_t)nb[q] * FD + j);
#pragma unroll
                for (int q = 0; q < 8; q++) {
                    float x = v[q];
#pragma unroll
                    for (int k = 0; k < 8; k++) { float mx = fmaxf(tk[k], x); x = fminf(tk[k], x); tk[k] = mx; }
                }
            }
            for (; i < cnt; i++) {
                float x = __ldg(nf + (size_t)g_nbr[node * DEG + i] * FD + j);
#pragma unroll
                for (int k = 0; k < 8; k++) { float mx = fmaxf(tk[k], x); x = fminf(tk[k], x); tk[k] = mx; }
            }
            for (i = cnt; i < 8; i++) {               // torch zero-pads rows before topk
                float x = 0.0f;
#pragma unroll
                for (int k = 0; k < 8; k++) { float mx = fmaxf(tk[k], x); x = fminf(tk[k], x); tk[k] = mx; }
            }

            float vals[9];
            vals[0] = nf[(size_t)node * FD + j];      // channel 0: self
#pragma unroll
            for (int k = 0; k < 8; k++) vals[1 + k] = tk[k];

            // transposed B'[k][x] = sel[c][x+t], k=c*9+t, x=j-t.
            // consecutive j -> consecutive x words -> conflict-free STS.
            // x in [120,128) is garbage-but-finite; its outputs are never stored.
#pragma unroll
            for (int c = 0; c < 9; c++) {
                float v = to_tf32(vals[c]);
#pragma unroll
                for (int t = 0; t < 9; t++) {
                    int x = j - t;
                    if (x >= 0)
                        sts32f(bw + (uint32_t)((c * 9 + t) * LDX + x) * 4, v);
                }
            }
            BAR_SYNC(1 + buf);                        // publish buffer
        }
    } else {
        // ======== CONSUMER (warps 0..7): M=32 x N=64 tiles, single-pass tf32 GEMM ======
        const int l4 = lane >> 2, lc = lane & 3;
        const int mg = wid & 3;                       // M group (32 rows)
        const int ng = wid >> 2;                      // N half (64 cols)
        const uint32_t A8   = 8u * LDBW * 4;          // 3200 B
        const uint32_t A16  = 16u * LDBW * 4;         // 6400 B
        const uint32_t KROW = LDX * 4;                // 528 B
        const uint32_t aRow = sa + OFF_A + (uint32_t)((mg * 32 + l4) * LDBW + lc) * 4;
        const uint32_t bColOff = (uint32_t)(ng * 64 + l4) * 4 + (uint32_t)lc * KROW;

        for (int node = blockIdx.x; node < NN; node += gridDim.x, ++it) {
            const int buf = it & 1;
            BAR_SYNC(1 + buf);                        // wait buffer full

            const uint32_t bCol = sa + OFF_B + (uint32_t)buf * BUF_BYTES + bColOff;

            float C[2][8][4];
#pragma unroll
            for (int mt = 0; mt < 2; mt++)
#pragma unroll
                for (int g = 0; g < 8; g++)
                    C[mt][g][0] = C[mt][g][1] = C[mt][g][2] = C[mt][g][3] = 0.f;

#pragma unroll
            for (int ks = 0; ks < KP / 8; ks++) {
                const uint32_t kb = (uint32_t)ks * 32;
                const uint32_t bk = (uint32_t)ks * 8 * KROW;
                uint32_t a[2][4];
#pragma unroll
                for (int mt = 0; mt < 2; mt++) {
                    const uint32_t ar = aRow + (uint32_t)mt * A16;
                    a[mt][0] = lds32(ar + kb);        a[mt][1] = lds32(ar + A8 + kb);
                    a[mt][2] = lds32(ar + kb + 16);   a[mt][3] = lds32(ar + A8 + kb + 16);
                }
                uint32_t bf[8][2];
#pragma unroll
                for (int g = 0; g < 8; g++) {
                    bf[g][0] = lds32(bCol + bk + (uint32_t)g * 32);
                    bf[g][1] = lds32(bCol + bk + 4 * KROW + (uint32_t)g * 32);
                }
#pragma unroll
                for (int g = 0; g < 8; g++) {
                    mma_tf32(C[0][g], a[0], bf[g][0], bf[g][1]);
                    mma_tf32(C[1][g], a[1], bf[g][0], bf[g][1]);
                }
            }

            // ---- epilogue: +bias, float2 stores; skip the N-pad tile (x>=120) ----
            float* base = out + (size_t)node * (OUTC * XO);
            const int gmax = (ng == 1) ? 7 : 8;       // ng=1,g=7 covers x 120..127
#pragma unroll
            for (int mt = 0; mt < 2; mt++) {
                const int o0 = mg * 32 + mt * 16 + l4;
                const int o1 = o0 + 8;
                const float b0 = bias_s[o0], b1 = bias_s[o1];
                float* r0 = base + o0 * XO + ng * 64 + 2 * lc;
                float* r1 = base + o1 * XO + ng * 64 + 2 * lc;
                for (int g = 0; g < gmax; g++) {
                    *reinterpret_cast<float2*>(r0 + g * 8) =
                        make_float2(C[mt][g][0] + b0, C[mt][g][1] + b0);
                    *reinterpret_cast<float2*>(r1 + g * 8) =
                        make_float2(C[mt][g][2] + b1, C[mt][g][3] + b1);
                }
            }
            // buffer reuse safety: producer refills `buf` only after it reaches
            // BAR(1+buf) again, strictly after this consumer's arrival there.
        }
    }
}

extern "C" void kernel_launch(void* const* d_in, const int* in_sizes, int n_in,
                              void* d_out, int out_size) {
    const float* nf  = (const float*)d_in[0];
    const int*   adj = (const int*)d_in[1];
    const float* cw  = (const float*)d_in[2];
    const float* cb  = (const float*)d_in[3];
    float* out = (float*)d_out;
    (void)in_sizes; (void)n_in; (void)out_size;

    cudaFuncSetAttribute(lgcl_tf32, cudaFuncAttributeMaxDynamicSharedMemorySize, SMEM_TOT);

    build_nbr<<<NN, 256>>>(adj);
    lgcl_tf32<<<152, NTH, SMEM_TOT>>>(nf, cw, cb, out);
}